// round 1
// baseline (speedup 1.0000x reference)
#include <cuda_runtime.h>
#include <math.h>

#define Bdim 8
#define Vn   256
#define Hn   128
#define NR   2048      /* B*V   */
#define NE   524288    /* B*V*V */

// ---------------- device scratch (no allocation allowed) ----------------
__device__ float g_Uh[NR * Hn];
__device__ float g_Vh[NR * Hn];
__device__ float g_Ah[NR * Hn];
__device__ float g_Bh[NR * Hn];
__device__ float g_hnew[NR * Hn];
__device__ float g_esum[Hn];
__device__ float g_esq[Hn];
__device__ float g_escale[Hn];
__device__ float g_eshift[Hn];
__device__ float g_enew[(size_t)NE * Hn];   // 268 MB spill of e_new

// ---------------- kernels ----------------

__global__ void k_zero() {
    int t = threadIdx.x;
    if (t < Hn) { g_esum[t] = 0.f; g_esq[t] = 0.f; }
}

// Uh/Vh/Ah/Bh = h @ W^T + b ; one block per (b,v) row, 128 threads.
__global__ void k_hlin(const float* __restrict__ h,
                       const float* __restrict__ Uw, const float* __restrict__ Ub,
                       const float* __restrict__ Vw, const float* __restrict__ Vb,
                       const float* __restrict__ Aw, const float* __restrict__ Ab,
                       const float* __restrict__ Bw, const float* __restrict__ Bb) {
    __shared__ float xs[Hn];
    int row = blockIdx.x, t = threadIdx.x;
    xs[t] = h[row * Hn + t];
    __syncthreads();
    float au = Ub[t], av = Vb[t], aa = Ab[t], ab = Bb[t];
    const float* ur = Uw + t * Hn;
    const float* vr = Vw + t * Hn;
    const float* ar = Aw + t * Hn;
    const float* br = Bw + t * Hn;
#pragma unroll 4
    for (int k = 0; k < Hn; k++) {
        float x = xs[k];
        au += x * ur[k]; av += x * vr[k]; aa += x * ar[k]; ab += x * br[k];
    }
    g_Uh[row * Hn + t] = au;
    g_Vh[row * Hn + t] = av;
    g_Ah[row * Hn + t] = aa;
    g_Bh[row * Hn + t] = ab;
}

// Main pass: one block per (b,i). Computes e_new row-panel [256 x 128]:
//   e_new = e @ Cw^T + Cb + Ah[b,j] + Bh[b,i]
// spills e_new, accumulates channel sums for BN, and does the masked
// sigmoid-gated aggregation over j -> h_new = Uh + agg.
extern "C" __global__ void k_emain(const float* __restrict__ e,
                                   const int* __restrict__ graph,
                                   const float* __restrict__ Cw,
                                   const float* __restrict__ Cb) {
    extern __shared__ float sm[];
    float* Wt  = sm;               // [128][129] transposed Cw, padded
    float* es  = Wt + 128 * 129;   // [16][128] e tile
    float* ahs = es + 2048;        // [16][128] Ah tile
    float* vhs = ahs + 2048;       // [16][128] Vh tile
    float* bhs = vhs + 2048;       // [128] Bh row + C bias folded
    float* red = bhs + 128;        // [256] reduce buffer
    int*   gs  = (int*)(red + 256);// [256] graph row

    int p = blockIdx.x;            // p = b*256 + i
    int b = p >> 8;
    int t = threadIdx.x;

    // stage Cw transposed: Wt[k][h], pad 129 kills bank conflicts both ways
    for (int idx = t; idx < Hn * Hn; idx += 256) {
        int hh = idx >> 7, kk = idx & 127;
        Wt[kk * 129 + hh] = Cw[idx];
    }
    if (t < Hn) bhs[t] = g_Bh[p * Hn + t] + Cb[t];
    gs[t] = graph[p * Vn + t];
    __syncthreads();

    int h = t & 127, jh = t >> 7;
    float aggLoc = 0.f, sumLoc = 0.f, sqLoc = 0.f;

    const float4* esrc = (const float4*)(e + (size_t)p * Vn * Hn);
    const float4* asrc = (const float4*)(g_Ah + (size_t)b * Vn * Hn);
    const float4* vsrc = (const float4*)(g_Vh + (size_t)b * Vn * Hn);

    for (int c = 0; c < 16; c++) {          // 16 chunks of 16 j-rows
        int jb = c * 16;
        int base = c * 512;                  // float4 offset of chunk
        ((float4*)es)[t]        = esrc[base + t];
        ((float4*)es)[t + 256]  = esrc[base + t + 256];
        ((float4*)ahs)[t]       = asrc[base + t];
        ((float4*)ahs)[t + 256] = asrc[base + t + 256];
        ((float4*)vhs)[t]       = vsrc[base + t];
        ((float4*)vhs)[t + 256] = vsrc[base + t + 256];
        __syncthreads();

        float acc[8];
#pragma unroll
        for (int r = 0; r < 8; r++) acc[r] = 0.f;

        const float* eb = es + jh * 8 * Hn;
        for (int k = 0; k < Hn; k++) {
            float w = Wt[k * 129 + h];       // conflict-free
            const float* ep = eb + k;        // broadcast reads
#pragma unroll
            for (int r = 0; r < 8; r++) acc[r] += ep[r * Hn] * w;
        }

#pragma unroll
        for (int r = 0; r < 8; r++) {
            int jl = jh * 8 + r;
            int j  = jb + jl;
            float en = acc[r] + ahs[jl * Hn + h] + bhs[h];
            g_enew[((size_t)p * Vn + j) * Hn + h] = en;
            sumLoc += en;
            sqLoc  += en * en;
            if (!gs[j]) {
                float gte = 1.0f / (1.0f + __expf(-en));
                aggLoc += gte * vhs[jl * Hn + h];
            }
        }
        __syncthreads();
    }

    red[t] = aggLoc; __syncthreads();
    if (t < Hn) g_hnew[p * Hn + t] = g_Uh[p * Hn + t] + red[t] + red[t + 128];
    __syncthreads();
    red[t] = sumLoc; __syncthreads();
    if (t < Hn) atomicAdd(&g_esum[t], red[t] + red[t + 128]);
    __syncthreads();
    red[t] = sqLoc; __syncthreads();
    if (t < Hn) atomicAdd(&g_esq[t], red[t] + red[t + 128]);
}

// h-side batchnorm + residual relu. One block per channel.
__global__ void k_hbn(const float* __restrict__ hin,
                      const float* __restrict__ gam,
                      const float* __restrict__ bet,
                      float* __restrict__ out) {
    int h = blockIdx.x, t = threadIdx.x;   // 256 threads
    float v[8];
    float s = 0.f, q = 0.f;
#pragma unroll
    for (int r = 0; r < 8; r++) {
        float x = g_hnew[(t * 8 + r) * Hn + h];
        v[r] = x; s += x; q += x * x;
    }
    __shared__ float rs[256], rq[256];
    rs[t] = s; rq[t] = q; __syncthreads();
    for (int o = 128; o > 0; o >>= 1) {
        if (t < o) { rs[t] += rs[t + o]; rq[t] += rq[t + o]; }
        __syncthreads();
    }
    __shared__ float sc, sh;
    if (t == 0) {
        float mean = rs[0] * (1.0f / NR);
        float var  = rq[0] * (1.0f / NR) - mean * mean;
        float scale = gam[h] * rsqrtf(var + 1e-5f);
        sc = scale; sh = bet[h] - mean * scale;
    }
    __syncthreads();
#pragma unroll
    for (int r = 0; r < 8; r++) {
        int row = t * 8 + r;
        float y = fmaxf(v[r] * sc + sh, 0.f);
        out[row * Hn + h] = hin[row * Hn + h] + y;
    }
}

__global__ void k_estats(const float* __restrict__ gam,
                         const float* __restrict__ bet) {
    int t = threadIdx.x;
    if (t < Hn) {
        float mean = g_esum[t] * (1.0f / NE);
        float var  = g_esq[t] * (1.0f / NE) - mean * mean;
        float scale = gam[t] * rsqrtf(var + 1e-5f);
        g_escale[t] = scale;
        g_eshift[t] = bet[t] - mean * scale;
    }
}

// pass 2 over e: normalize + relu + residual, vectorized float4
__global__ void k_epass2(const float* __restrict__ ein,
                         float* __restrict__ eout) {
    size_t idx = (size_t)blockIdx.x * blockDim.x + threadIdx.x;  // float4 idx
    int h0 = (int)((idx * 4) & 127);
    float4 x = ((const float4*)g_enew)[idx];
    float4 a = ((const float4*)ein)[idx];
    float4 o;
    o.x = a.x + fmaxf(x.x * g_escale[h0]     + g_eshift[h0],     0.f);
    o.y = a.y + fmaxf(x.y * g_escale[h0 + 1] + g_eshift[h0 + 1], 0.f);
    o.z = a.z + fmaxf(x.z * g_escale[h0 + 2] + g_eshift[h0 + 2], 0.f);
    o.w = a.w + fmaxf(x.w * g_escale[h0 + 3] + g_eshift[h0 + 3], 0.f);
    ((float4*)eout)[idx] = o;
}

// ---------------- launch ----------------
extern "C" void kernel_launch(void* const* d_in, const int* in_sizes, int n_in,
                              void* d_out, int out_size) {
    const float* h   = (const float*)d_in[0];
    const float* e   = (const float*)d_in[1];
    const int*   gra = (const int*)  d_in[2];
    const float* Uw  = (const float*)d_in[3],  *Ub = (const float*)d_in[4];
    const float* Vw  = (const float*)d_in[5],  *Vb = (const float*)d_in[6];
    const float* Aw  = (const float*)d_in[7],  *Ab = (const float*)d_in[8];
    const float* Bw  = (const float*)d_in[9],  *Bb = (const float*)d_in[10];
    const float* Cw  = (const float*)d_in[11], *Cb = (const float*)d_in[12];
    const float* gh  = (const float*)d_in[13], *bh = (const float*)d_in[14];
    const float* ge  = (const float*)d_in[15], *be = (const float*)d_in[16];

    float* out  = (float*)d_out;
    float* hout = out;                        // [2048,128]
    float* eout = out + (size_t)NR * Hn;      // [8,256,256,128]

    const int smemE = (128 * 129 + 3 * 2048 + 128 + 256 + 256) * 4;  // 93184 B
    cudaFuncSetAttribute(k_emain, cudaFuncAttributeMaxDynamicSharedMemorySize, smemE);

    k_zero  <<<1, 128>>>();
    k_hlin  <<<NR, 128>>>(h, Uw, Ub, Vw, Vb, Aw, Ab, Bw, Bb);
    k_emain <<<NR, 256, smemE>>>(e, gra, Cw, Cb);
    k_hbn   <<<Hn, 256>>>(h, gh, bh, hout);
    k_estats<<<1, 128>>>(ge, be);
    k_epass2<<<65536, 256>>>(e, eout);
}

// round 2
// speedup vs baseline: 1.2441x; 1.2441x over previous
#include <cuda_runtime.h>
#include <math.h>
#include <stdint.h>

#define Bdim 8
#define Vn   256
#define Hn   128
#define NR   2048      /* B*V   */
#define NE   524288    /* B*V*V */

// ---------------- device scratch (no allocation allowed) ----------------
__device__ float g_Uh[NR * Hn];
__device__ float g_Vh[NR * Hn];
__device__ float g_Ah[NR * Hn];
__device__ float g_Bh[NR * Hn];
__device__ float g_hnew[NR * Hn];
__device__ float g_esum[Hn];
__device__ float g_esq[Hn];
__device__ float g_escale[Hn];
__device__ float g_eshift[Hn];
__device__ float g_enew[(size_t)NE * Hn];   // 268 MB spill of e_new

// ---------------- helpers ----------------
__device__ __forceinline__ unsigned smem_u32(const void* p) {
    unsigned a;
    asm("{ .reg .u64 t; cvta.to.shared.u64 t, %1; cvt.u32.u64 %0, t; }"
        : "=r"(a) : "l"(p));
    return a;
}
__device__ __forceinline__ void cp_async16(unsigned dst, const void* src) {
    asm volatile("cp.async.cg.shared.global [%0], [%1], 16;\n" :: "r"(dst), "l"(src));
}
__device__ __forceinline__ uint32_t f2tf32(float f) {
    uint32_t u;
    asm("cvt.rna.tf32.f32 %0, %1;" : "=r"(u) : "f"(f));
    return u;
}
__device__ __forceinline__ float fast_sigmoid(float x) {
    float t;
    asm("tanh.approx.f32 %0, %1;" : "=f"(t) : "f"(0.5f * x));
    return 0.5f * t + 0.5f;
}

// ---------------- kernels ----------------

__global__ void k_zero() {
    int t = threadIdx.x;
    if (t < Hn) { g_esum[t] = 0.f; g_esq[t] = 0.f; }
}

// Uh/Vh/Ah/Bh = h @ W^T + b ; one block per (b,v) row, 128 threads.
__global__ void k_hlin(const float* __restrict__ h,
                       const float* __restrict__ Uw, const float* __restrict__ Ub,
                       const float* __restrict__ Vw, const float* __restrict__ Vb,
                       const float* __restrict__ Aw, const float* __restrict__ Ab,
                       const float* __restrict__ Bw, const float* __restrict__ Bb) {
    __shared__ float xs[Hn];
    int row = blockIdx.x, t = threadIdx.x;
    xs[t] = h[row * Hn + t];
    __syncthreads();
    float au = Ub[t], av = Vb[t], aa = Ab[t], ab = Bb[t];
    const float* ur = Uw + t * Hn;
    const float* vr = Vw + t * Hn;
    const float* ar = Aw + t * Hn;
    const float* br = Bw + t * Hn;
#pragma unroll 4
    for (int k = 0; k < Hn; k++) {
        float x = xs[k];
        au += x * ur[k]; av += x * vr[k]; aa += x * ar[k]; ab += x * br[k];
    }
    g_Uh[row * Hn + t] = au;
    g_Vh[row * Hn + t] = av;
    g_Ah[row * Hn + t] = aa;
    g_Bh[row * Hn + t] = ab;
}

// Main pass, tf32 tensor-core version.
// One block per p=(b,i). 512 threads = 16 warps (4 row-groups x 4 col-groups),
// warp tile 32x32, j processed in 2 chunks of 128 rows, K=128 (16 ksteps).
// smem layout (floats):
//   WtS  [0,17408)        Cw^T, tf32 bits, Wt[k*136+n]
//   As   [17408,51200)    2 x (128 rows x stride 132) e chunk buffers
//   sumS [51200,51328) sqS [51328,51456) aggS [51456,51584)
//   gs   [51584,51840)    graph row (int)
#define WT_STRIDE 136
#define AS_STRIDE 132
#define AS_OFF    17408
#define AS_BUF    16896
#define SUM_OFF   51200
#define SMEM_FLOATS 51840

__global__ __launch_bounds__(512, 1)
void k_emain(const float* __restrict__ e,
             const int* __restrict__ graph,
             const float* __restrict__ Cw,
             const float* __restrict__ Cb) {
    extern __shared__ float sm[];
    uint32_t* WtS = (uint32_t*)sm;
    float* As   = sm + AS_OFF;
    float* sumS = sm + SUM_OFF;
    float* sqS  = sumS + 128;
    float* aggS = sqS + 128;
    int*   gs   = (int*)(aggS + 128);

    const int p = blockIdx.x;          // b*256 + i
    const int b = p >> 8;
    const int t = threadIdx.x;
    const int lane = t & 31;
    const int wid  = t >> 5;
    const int wr = wid >> 2;           // row group 0..3 (rows wr*32..)
    const int wc = wid & 3;            // col group 0..3 (cols wc*32..)
    const int gid = lane >> 2;         // 0..7
    const int tig = lane & 3;          // 0..3

    // ---- prologue ----
    for (int i = t; i < Hn * Hn; i += 512) {    // stage Cw^T as tf32
        int n = i >> 7, k = i & 127;
        WtS[k * WT_STRIDE + n] = f2tf32(Cw[i]);
    }
    if (t < 256) gs[t] = graph[p * Vn + t];
    if (t < 128) { sumS[t] = 0.f; sqS[t] = 0.f; aggS[t] = 0.f; }

    // per-thread bias (Bh[p] + Cb) for this thread's 8 h-columns
    float bh8[8];
#pragma unroll
    for (int q = 0; q < 4; q++) {
        int h = wc * 32 + q * 8 + tig * 2;
        float2 bb = *(const float2*)(g_Bh + p * Hn + h);
        float2 cb = *(const float2*)(Cb + h);
        bh8[q * 2]     = bb.x + cb.x;
        bh8[q * 2 + 1] = bb.y + cb.y;
    }

    float sum8[8], sq8[8], agg8[8];
#pragma unroll
    for (int i = 0; i < 8; i++) { sum8[i] = 0.f; sq8[i] = 0.f; agg8[i] = 0.f; }

    // issue chunk 0 stage (128 rows x 128 floats = 4096 float4)
    const float* ebase = e + (size_t)p * Vn * Hn;
    {
        unsigned dbase = smem_u32(As);
#pragma unroll
        for (int i = 0; i < 8; i++) {
            int fid = i * 512 + t;
            int row = fid >> 5, kq = fid & 31;
            cp_async16(dbase + (row * AS_STRIDE + kq * 4) * 4,
                       ebase + (size_t)row * Hn + kq * 4);
        }
        asm volatile("cp.async.commit_group;\n");
    }

    for (int c = 0; c < 2; c++) {
        if (c == 0) {
            // prefetch chunk 1 into buffer 1
            unsigned dbase = smem_u32(As + AS_BUF);
#pragma unroll
            for (int i = 0; i < 8; i++) {
                int fid = i * 512 + t;
                int row = fid >> 5, kq = fid & 31;
                cp_async16(dbase + (row * AS_STRIDE + kq * 4) * 4,
                           ebase + (size_t)(128 + row) * Hn + kq * 4);
            }
            asm volatile("cp.async.commit_group;\n");
            asm volatile("cp.async.wait_group 1;\n");
        } else {
            asm volatile("cp.async.wait_group 0;\n");
        }
        __syncthreads();

        const float* Ab = As + c * AS_BUF;
        const int jb = c * 128;

        // ---- GEMM: C[32x32] per warp, K=128 ----
        float cf[2][4][4];
#pragma unroll
        for (int rg = 0; rg < 2; rg++)
#pragma unroll
            for (int nt = 0; nt < 4; nt++)
#pragma unroll
                for (int q = 0; q < 4; q++) cf[rg][nt][q] = 0.f;

#pragma unroll 2
        for (int ks = 0; ks < 16; ks++) {
            int k0 = ks * 8 + tig;
            uint32_t a[2][4];
#pragma unroll
            for (int rg = 0; rg < 2; rg++) {
                int r = wr * 32 + rg * 16 + gid;
                a[rg][0] = f2tf32(Ab[r * AS_STRIDE + k0]);
                a[rg][1] = f2tf32(Ab[(r + 8) * AS_STRIDE + k0]);
                a[rg][2] = f2tf32(Ab[r * AS_STRIDE + k0 + 4]);
                a[rg][3] = f2tf32(Ab[(r + 8) * AS_STRIDE + k0 + 4]);
            }
            uint32_t bfr[4][2];
#pragma unroll
            for (int nt = 0; nt < 4; nt++) {
                int n = wc * 32 + nt * 8 + gid;
                bfr[nt][0] = WtS[k0 * WT_STRIDE + n];
                bfr[nt][1] = WtS[(k0 + 4) * WT_STRIDE + n];
            }
#pragma unroll
            for (int rg = 0; rg < 2; rg++)
#pragma unroll
                for (int nt = 0; nt < 4; nt++) {
                    asm volatile(
                        "mma.sync.aligned.m16n8k8.row.col.f32.tf32.tf32.f32 "
                        "{%0,%1,%2,%3},{%4,%5,%6,%7},{%8,%9},{%0,%1,%2,%3};"
                        : "+f"(cf[rg][nt][0]), "+f"(cf[rg][nt][1]),
                          "+f"(cf[rg][nt][2]), "+f"(cf[rg][nt][3])
                        : "r"(a[rg][0]), "r"(a[rg][1]), "r"(a[rg][2]), "r"(a[rg][3]),
                          "r"(bfr[nt][0]), "r"(bfr[nt][1]));
                }
        }

        // ---- fused epilogue ----
#pragma unroll
        for (int rg = 0; rg < 2; rg++) {
#pragma unroll
            for (int half = 0; half < 2; half++) {
                int jl = wr * 32 + rg * 16 + gid + half * 8;
                int j  = jb + jl;
                int gmask = gs[j];
                const float* Ap = g_Ah + ((size_t)(b * Vn + j)) * Hn;
                const float* Vp = g_Vh + ((size_t)(b * Vn + j)) * Hn;
                float* Ep = g_enew + ((size_t)p * Vn + j) * Hn;
#pragma unroll
                for (int nt = 0; nt < 4; nt++) {
                    int h = wc * 32 + nt * 8 + tig * 2;
                    float2 ah = *(const float2*)(Ap + h);
                    float2 vh = *(const float2*)(Vp + h);
                    float en0 = cf[rg][nt][half * 2]     + ah.x + bh8[nt * 2];
                    float en1 = cf[rg][nt][half * 2 + 1] + ah.y + bh8[nt * 2 + 1];
                    *(float2*)(Ep + h) = make_float2(en0, en1);
                    sum8[nt * 2]     += en0;
                    sum8[nt * 2 + 1] += en1;
                    sq8[nt * 2]      += en0 * en0;
                    sq8[nt * 2 + 1]  += en1 * en1;
                    if (!gmask) {
                        agg8[nt * 2]     += fast_sigmoid(en0) * vh.x;
                        agg8[nt * 2 + 1] += fast_sigmoid(en1) * vh.y;
                    }
                }
            }
        }
        __syncthreads();
    }

    // ---- block reduction of per-channel stats ----
#pragma unroll
    for (int i = 0; i < 8; i++) {
        int h = wc * 32 + (i >> 1) * 8 + tig * 2 + (i & 1);
        atomicAdd(&sumS[h], sum8[i]);
        atomicAdd(&sqS[h],  sq8[i]);
        atomicAdd(&aggS[h], agg8[i]);
    }
    __syncthreads();
    if (t < Hn) {
        atomicAdd(&g_esum[t], sumS[t]);
        atomicAdd(&g_esq[t],  sqS[t]);
        g_hnew[p * Hn + t] = g_Uh[p * Hn + t] + aggS[t];
    }
}

// h-side batchnorm + residual relu. One block per channel.
__global__ void k_hbn(const float* __restrict__ hin,
                      const float* __restrict__ gam,
                      const float* __restrict__ bet,
                      float* __restrict__ out) {
    int h = blockIdx.x, t = threadIdx.x;   // 256 threads
    float v[8];
    float s = 0.f, q = 0.f;
#pragma unroll
    for (int r = 0; r < 8; r++) {
        float x = g_hnew[(t * 8 + r) * Hn + h];
        v[r] = x; s += x; q += x * x;
    }
    __shared__ float rs[256], rq[256];
    rs[t] = s; rq[t] = q; __syncthreads();
    for (int o = 128; o > 0; o >>= 1) {
        if (t < o) { rs[t] += rs[t + o]; rq[t] += rq[t + o]; }
        __syncthreads();
    }
    __shared__ float sc, sh;
    if (t == 0) {
        float mean = rs[0] * (1.0f / NR);
        float var  = rq[0] * (1.0f / NR) - mean * mean;
        float scale = gam[h] * rsqrtf(var + 1e-5f);
        sc = scale; sh = bet[h] - mean * scale;
    }
    __syncthreads();
#pragma unroll
    for (int r = 0; r < 8; r++) {
        int row = t * 8 + r;
        float y = fmaxf(v[r] * sc + sh, 0.f);
        out[row * Hn + h] = hin[row * Hn + h] + y;
    }
}

__global__ void k_estats(const float* __restrict__ gam,
                         const float* __restrict__ bet) {
    int t = threadIdx.x;
    if (t < Hn) {
        float mean = g_esum[t] * (1.0f / NE);
        float var  = g_esq[t] * (1.0f / NE) - mean * mean;
        float scale = gam[t] * rsqrtf(var + 1e-5f);
        g_escale[t] = scale;
        g_eshift[t] = bet[t] - mean * scale;
    }
}

// pass 2 over e: normalize + relu + residual, vectorized float4
__global__ void k_epass2(const float* __restrict__ ein,
                         float* __restrict__ eout) {
    size_t idx = (size_t)blockIdx.x * blockDim.x + threadIdx.x;  // float4 idx
    int h0 = (int)((idx * 4) & 127);
    float4 x = ((const float4*)g_enew)[idx];
    float4 a = ((const float4*)ein)[idx];
    float4 o;
    o.x = a.x + fmaxf(x.x * g_escale[h0]     + g_eshift[h0],     0.f);
    o.y = a.y + fmaxf(x.y * g_escale[h0 + 1] + g_eshift[h0 + 1], 0.f);
    o.z = a.z + fmaxf(x.z * g_escale[h0 + 2] + g_eshift[h0 + 2], 0.f);
    o.w = a.w + fmaxf(x.w * g_escale[h0 + 3] + g_eshift[h0 + 3], 0.f);
    ((float4*)eout)[idx] = o;
}

// ---------------- launch ----------------
extern "C" void kernel_launch(void* const* d_in, const int* in_sizes, int n_in,
                              void* d_out, int out_size) {
    const float* h   = (const float*)d_in[0];
    const float* e   = (const float*)d_in[1];
    const int*   gra = (const int*)  d_in[2];
    const float* Uw  = (const float*)d_in[3],  *Ub = (const float*)d_in[4];
    const float* Vw  = (const float*)d_in[5],  *Vb = (const float*)d_in[6];
    const float* Aw  = (const float*)d_in[7],  *Ab = (const float*)d_in[8];
    const float* Bw  = (const float*)d_in[9],  *Bb = (const float*)d_in[10];
    const float* Cw  = (const float*)d_in[11], *Cb = (const float*)d_in[12];
    const float* gh  = (const float*)d_in[13], *bh = (const float*)d_in[14];
    const float* ge  = (const float*)d_in[15], *be = (const float*)d_in[16];

    float* out  = (float*)d_out;
    float* hout = out;                        // [2048,128]
    float* eout = out + (size_t)NR * Hn;      // [8,256,256,128]

    const int smemE = SMEM_FLOATS * 4;        // 207360 B
    static int cfgDone = 0;
    if (!cfgDone) {
        cudaFuncSetAttribute(k_emain, cudaFuncAttributeMaxDynamicSharedMemorySize, smemE);
        cfgDone = 1;
    }

    k_zero  <<<1, 128>>>();
    k_hlin  <<<NR, 128>>>(h, Uw, Ub, Vw, Vb, Aw, Ab, Bw, Bb);
    k_emain <<<NR, 512, smemE>>>(e, gra, Cw, Cb);
    k_hbn   <<<Hn, 256>>>(h, gh, bh, hout);
    k_estats<<<1, 128>>>(ge, be);
    k_epass2<<<65536, 256>>>(e, eout);
}

// round 3
// speedup vs baseline: 1.7967x; 1.4442x over previous
#include <cuda_runtime.h>
#include <math.h>
#include <stdint.h>

#define Bdim 8
#define Vn   256
#define Hn   128
#define NR   2048      /* B*V   */
#define NE   524288    /* B*V*V */

// ---------------- device scratch (no allocation allowed) ----------------
__device__ float g_Uh[NR * Hn];
__device__ float g_Vh[NR * Hn];
__device__ float g_Ah[NR * Hn];
__device__ float g_Bh[NR * Hn];
__device__ float g_hnew[NR * Hn];
__device__ float g_esum[Hn];
__device__ float g_esq[Hn];
__device__ float g_escale[Hn];
__device__ float g_eshift[Hn];

// ---------------- helpers ----------------
__device__ __forceinline__ unsigned smem_u32(const void* p) {
    unsigned a;
    asm("{ .reg .u64 t; cvta.to.shared.u64 t, %1; cvt.u32.u64 %0, t; }"
        : "=r"(a) : "l"(p));
    return a;
}
__device__ __forceinline__ void cp_async16(unsigned dst, const void* src) {
    asm volatile("cp.async.cg.shared.global [%0], [%1], 16;\n" :: "r"(dst), "l"(src));
}
__device__ __forceinline__ uint32_t f2tf32(float f) {
    uint32_t u;
    asm("cvt.rna.tf32.f32 %0, %1;" : "=r"(u) : "f"(f));
    return u;
}
__device__ __forceinline__ float fast_sigmoid(float x) {
    float t;
    asm("tanh.approx.f32 %0, %1;" : "=f"(t) : "f"(0.5f * x));
    return 0.5f * t + 0.5f;
}

// ---------------- kernels ----------------

__global__ void k_zero() {
    int t = threadIdx.x;
    if (t < Hn) { g_esum[t] = 0.f; g_esq[t] = 0.f; }
}

// Uh/Vh/Ah/Bh = h @ W^T + b. Tiled, coalesced.
// 128 blocks x 256 threads; block handles 16 rows. Per array: stage W in smem
// (stride 132, float4), thread computes 2 rows x 4 cols.
#define HL_STR 132
__global__ __launch_bounds__(256)
void k_hlin(const float* __restrict__ h,
            const float* __restrict__ Uw, const float* __restrict__ Ub,
            const float* __restrict__ Vw, const float* __restrict__ Vb,
            const float* __restrict__ Aw, const float* __restrict__ Ab,
            const float* __restrict__ Bw, const float* __restrict__ Bb) {
    __shared__ float hs[16 * HL_STR];
    __shared__ float Ws[128 * HL_STR];
    const int t = threadIdx.x;
    const int lane = t & 31, wq = t >> 5;
    const int rbase = blockIdx.x * 16;

    // stage h tile (16 x 128)
    {
        int idx0 = t, idx1 = t + 256;
        int r0 = idx0 >> 5, kq0 = idx0 & 31;
        int r1 = idx1 >> 5, kq1 = idx1 & 31;
        *(float4*)(hs + r0 * HL_STR + kq0 * 4) = *(const float4*)(h + (size_t)(rbase + r0) * Hn + kq0 * 4);
        *(float4*)(hs + r1 * HL_STR + kq1 * 4) = *(const float4*)(h + (size_t)(rbase + r1) * Hn + kq1 * 4);
    }

    const float* Wp[4] = {Uw, Vw, Aw, Bw};
    const float* bp[4] = {Ub, Vb, Ab, Bb};
    float* Op[4];
    Op[0] = g_Uh; Op[1] = g_Vh; Op[2] = g_Ah; Op[3] = g_Bh;

    const int r0 = wq * 2, r1 = wq * 2 + 1;

    for (int a = 0; a < 4; a++) {
        __syncthreads();
        // stage W (128 x 128), coalesced float4
        const float* W = Wp[a];
#pragma unroll
        for (int i = 0; i < 16; i++) {
            int idx = t + i * 256;
            int o = idx >> 5, kq = idx & 31;
            *(float4*)(Ws + o * HL_STR + kq * 4) = *(const float4*)(W + (size_t)o * Hn + kq * 4);
        }
        __syncthreads();

        float acc0[4] = {0.f, 0.f, 0.f, 0.f};
        float acc1[4] = {0.f, 0.f, 0.f, 0.f};
#pragma unroll 4
        for (int k4 = 0; k4 < 32; k4++) {
            float4 h0 = *(const float4*)(hs + r0 * HL_STR + k4 * 4);
            float4 h1 = *(const float4*)(hs + r1 * HL_STR + k4 * 4);
#pragma unroll
            for (int c = 0; c < 4; c++) {
                float4 w = *(const float4*)(Ws + (lane + 32 * c) * HL_STR + k4 * 4);
                acc0[c] += h0.x * w.x + h0.y * w.y + h0.z * w.z + h0.w * w.w;
                acc1[c] += h1.x * w.x + h1.y * w.y + h1.z * w.z + h1.w * w.w;
            }
        }
        float* O = Op[a];
        const float* bb = bp[a];
#pragma unroll
        for (int c = 0; c < 4; c++) {
            int col = lane + 32 * c;
            float bv = bb[col];
            O[(size_t)(rbase + r0) * Hn + col] = acc0[c] + bv;
            O[(size_t)(rbase + r1) * Hn + col] = acc1[c] + bv;
        }
    }
}

// shared GEMM scaffolding for pass1/pass2:
// One block per p=(b,i). 512 threads = 16 warps (4x4), warp tile 32x32,
// j in 2 chunks of 128 rows, K=128 (16 ksteps of k8), tf32 mma.
#define WT_STRIDE 136
#define AS_STRIDE 132
#define AS_OFF    17408
#define AS_BUF    16896
#define SUM_OFF   51200
#define SMEM_FLOATS 51840

// Pass 1: compute e_new on the fly; accumulate BN stats (sum, sumsq) and the
// masked sigmoid-gated aggregation -> g_hnew. No spill of e_new.
__global__ __launch_bounds__(512, 1)
void k_pass1(const float* __restrict__ e,
             const int* __restrict__ graph,
             const float* __restrict__ Cw,
             const float* __restrict__ Cb) {
    extern __shared__ float sm[];
    uint32_t* WtS = (uint32_t*)sm;
    float* As   = sm + AS_OFF;
    float* sumS = sm + SUM_OFF;
    float* sqS  = sumS + 128;
    float* aggS = sqS + 128;
    int*   gs   = (int*)(aggS + 128);

    const int p = blockIdx.x;
    const int b = p >> 8;
    const int t = threadIdx.x;
    const int lane = t & 31;
    const int wid  = t >> 5;
    const int wr = wid >> 2, wc = wid & 3;
    const int gid = lane >> 2, tig = lane & 3;

    for (int i = t; i < Hn * Hn; i += 512) {
        int n = i >> 7, k = i & 127;
        WtS[k * WT_STRIDE + n] = f2tf32(Cw[i]);
    }
    if (t < 256) gs[t] = graph[p * Vn + t];
    if (t < 128) { sumS[t] = 0.f; sqS[t] = 0.f; aggS[t] = 0.f; }

    float bh8[8];
#pragma unroll
    for (int q = 0; q < 4; q++) {
        int h = wc * 32 + q * 8 + tig * 2;
        float2 bb = *(const float2*)(g_Bh + p * Hn + h);
        float2 cb = *(const float2*)(Cb + h);
        bh8[q * 2]     = bb.x + cb.x;
        bh8[q * 2 + 1] = bb.y + cb.y;
    }

    float sum8[8], sq8[8], agg8[8];
#pragma unroll
    for (int i = 0; i < 8; i++) { sum8[i] = 0.f; sq8[i] = 0.f; agg8[i] = 0.f; }

    const float* ebase = e + (size_t)p * Vn * Hn;
    {
        unsigned dbase = smem_u32(As);
#pragma unroll
        for (int i = 0; i < 8; i++) {
            int fid = i * 512 + t;
            int row = fid >> 5, kq = fid & 31;
            cp_async16(dbase + (row * AS_STRIDE + kq * 4) * 4,
                       ebase + (size_t)row * Hn + kq * 4);
        }
        asm volatile("cp.async.commit_group;\n");
    }

    for (int c = 0; c < 2; c++) {
        if (c == 0) {
            unsigned dbase = smem_u32(As + AS_BUF);
#pragma unroll
            for (int i = 0; i < 8; i++) {
                int fid = i * 512 + t;
                int row = fid >> 5, kq = fid & 31;
                cp_async16(dbase + (row * AS_STRIDE + kq * 4) * 4,
                           ebase + (size_t)(128 + row) * Hn + kq * 4);
            }
            asm volatile("cp.async.commit_group;\n");
            asm volatile("cp.async.wait_group 1;\n");
        } else {
            asm volatile("cp.async.wait_group 0;\n");
        }
        __syncthreads();

        const float* Abuf = As + c * AS_BUF;
        const int jb = c * 128;

        float cf[2][4][4];
#pragma unroll
        for (int rg = 0; rg < 2; rg++)
#pragma unroll
            for (int nt = 0; nt < 4; nt++)
#pragma unroll
                for (int q = 0; q < 4; q++) cf[rg][nt][q] = 0.f;

#pragma unroll 2
        for (int ks = 0; ks < 16; ks++) {
            int k0 = ks * 8 + tig;
            uint32_t a[2][4];
#pragma unroll
            for (int rg = 0; rg < 2; rg++) {
                int r = wr * 32 + rg * 16 + gid;
                a[rg][0] = f2tf32(Abuf[r * AS_STRIDE + k0]);
                a[rg][1] = f2tf32(Abuf[(r + 8) * AS_STRIDE + k0]);
                a[rg][2] = f2tf32(Abuf[r * AS_STRIDE + k0 + 4]);
                a[rg][3] = f2tf32(Abuf[(r + 8) * AS_STRIDE + k0 + 4]);
            }
            uint32_t bfr[4][2];
#pragma unroll
            for (int nt = 0; nt < 4; nt++) {
                int n = wc * 32 + nt * 8 + gid;
                bfr[nt][0] = WtS[k0 * WT_STRIDE + n];
                bfr[nt][1] = WtS[(k0 + 4) * WT_STRIDE + n];
            }
#pragma unroll
            for (int rg = 0; rg < 2; rg++)
#pragma unroll
                for (int nt = 0; nt < 4; nt++) {
                    asm volatile(
                        "mma.sync.aligned.m16n8k8.row.col.f32.tf32.tf32.f32 "
                        "{%0,%1,%2,%3},{%4,%5,%6,%7},{%8,%9},{%0,%1,%2,%3};"
                        : "+f"(cf[rg][nt][0]), "+f"(cf[rg][nt][1]),
                          "+f"(cf[rg][nt][2]), "+f"(cf[rg][nt][3])
                        : "r"(a[rg][0]), "r"(a[rg][1]), "r"(a[rg][2]), "r"(a[rg][3]),
                          "r"(bfr[nt][0]), "r"(bfr[nt][1]));
                }
        }

#pragma unroll
        for (int rg = 0; rg < 2; rg++) {
#pragma unroll
            for (int half = 0; half < 2; half++) {
                int jl = wr * 32 + rg * 16 + gid + half * 8;
                int j  = jb + jl;
                int gmask = gs[j];
                const float* Ap = g_Ah + ((size_t)(b * Vn + j)) * Hn;
                const float* Vp = g_Vh + ((size_t)(b * Vn + j)) * Hn;
#pragma unroll
                for (int nt = 0; nt < 4; nt++) {
                    int h = wc * 32 + nt * 8 + tig * 2;
                    float2 ah = *(const float2*)(Ap + h);
                    float2 vh = *(const float2*)(Vp + h);
                    float en0 = cf[rg][nt][half * 2]     + ah.x + bh8[nt * 2];
                    float en1 = cf[rg][nt][half * 2 + 1] + ah.y + bh8[nt * 2 + 1];
                    sum8[nt * 2]     += en0;
                    sum8[nt * 2 + 1] += en1;
                    sq8[nt * 2]      += en0 * en0;
                    sq8[nt * 2 + 1]  += en1 * en1;
                    if (!gmask) {
                        agg8[nt * 2]     += fast_sigmoid(en0) * vh.x;
                        agg8[nt * 2 + 1] += fast_sigmoid(en1) * vh.y;
                    }
                }
            }
        }
        __syncthreads();
    }

#pragma unroll
    for (int i = 0; i < 8; i++) {
        int h = wc * 32 + (i >> 1) * 8 + tig * 2 + (i & 1);
        atomicAdd(&sumS[h], sum8[i]);
        atomicAdd(&sqS[h],  sq8[i]);
        atomicAdd(&aggS[h], agg8[i]);
    }
    __syncthreads();
    if (t < Hn) {
        atomicAdd(&g_esum[t], sumS[t]);
        atomicAdd(&g_esq[t],  sqS[t]);
        g_hnew[p * Hn + t] = g_Uh[p * Hn + t] + aggS[t];
    }
}

// Pass 2: recompute e_new, apply BN scale/shift + relu + residual (residual
// read from the staged smem tile — no extra DRAM read), write e_out.
__global__ __launch_bounds__(512, 1)
void k_pass2(const float* __restrict__ e,
             const float* __restrict__ Cw,
             const float* __restrict__ Cb,
             float* __restrict__ eout) {
    extern __shared__ float sm[];
    uint32_t* WtS = (uint32_t*)sm;
    float* As = sm + AS_OFF;

    const int p = blockIdx.x;
    const int b = p >> 8;
    const int t = threadIdx.x;
    const int lane = t & 31;
    const int wid  = t >> 5;
    const int wr = wid >> 2, wc = wid & 3;
    const int gid = lane >> 2, tig = lane & 3;

    for (int i = t; i < Hn * Hn; i += 512) {
        int n = i >> 7, k = i & 127;
        WtS[k * WT_STRIDE + n] = f2tf32(Cw[i]);
    }

    float bh8[8], sc8[8], sh8[8];
#pragma unroll
    for (int q = 0; q < 4; q++) {
        int h = wc * 32 + q * 8 + tig * 2;
        float2 bb = *(const float2*)(g_Bh + p * Hn + h);
        float2 cb = *(const float2*)(Cb + h);
        float2 sc = *(const float2*)(g_escale + h);
        float2 sh = *(const float2*)(g_eshift + h);
        bh8[q * 2]     = bb.x + cb.x;
        bh8[q * 2 + 1] = bb.y + cb.y;
        sc8[q * 2]     = sc.x;  sc8[q * 2 + 1] = sc.y;
        sh8[q * 2]     = sh.x;  sh8[q * 2 + 1] = sh.y;
    }

    const float* ebase = e + (size_t)p * Vn * Hn;
    {
        unsigned dbase = smem_u32(As);
#pragma unroll
        for (int i = 0; i < 8; i++) {
            int fid = i * 512 + t;
            int row = fid >> 5, kq = fid & 31;
            cp_async16(dbase + (row * AS_STRIDE + kq * 4) * 4,
                       ebase + (size_t)row * Hn + kq * 4);
        }
        asm volatile("cp.async.commit_group;\n");
    }

    for (int c = 0; c < 2; c++) {
        if (c == 0) {
            unsigned dbase = smem_u32(As + AS_BUF);
#pragma unroll
            for (int i = 0; i < 8; i++) {
                int fid = i * 512 + t;
                int row = fid >> 5, kq = fid & 31;
                cp_async16(dbase + (row * AS_STRIDE + kq * 4) * 4,
                           ebase + (size_t)(128 + row) * Hn + kq * 4);
            }
            asm volatile("cp.async.commit_group;\n");
            asm volatile("cp.async.wait_group 1;\n");
        } else {
            asm volatile("cp.async.wait_group 0;\n");
        }
        __syncthreads();

        const float* Abuf = As + c * AS_BUF;
        const int jb = c * 128;

        float cf[2][4][4];
#pragma unroll
        for (int rg = 0; rg < 2; rg++)
#pragma unroll
            for (int nt = 0; nt < 4; nt++)
#pragma unroll
                for (int q = 0; q < 4; q++) cf[rg][nt][q] = 0.f;

#pragma unroll 2
        for (int ks = 0; ks < 16; ks++) {
            int k0 = ks * 8 + tig;
            uint32_t a[2][4];
#pragma unroll
            for (int rg = 0; rg < 2; rg++) {
                int r = wr * 32 + rg * 16 + gid;
                a[rg][0] = f2tf32(Abuf[r * AS_STRIDE + k0]);
                a[rg][1] = f2tf32(Abuf[(r + 8) * AS_STRIDE + k0]);
                a[rg][2] = f2tf32(Abuf[r * AS_STRIDE + k0 + 4]);
                a[rg][3] = f2tf32(Abuf[(r + 8) * AS_STRIDE + k0 + 4]);
            }
            uint32_t bfr[4][2];
#pragma unroll
            for (int nt = 0; nt < 4; nt++) {
                int n = wc * 32 + nt * 8 + gid;
                bfr[nt][0] = WtS[k0 * WT_STRIDE + n];
                bfr[nt][1] = WtS[(k0 + 4) * WT_STRIDE + n];
            }
#pragma unroll
            for (int rg = 0; rg < 2; rg++)
#pragma unroll
                for (int nt = 0; nt < 4; nt++) {
                    asm volatile(
                        "mma.sync.aligned.m16n8k8.row.col.f32.tf32.tf32.f32 "
                        "{%0,%1,%2,%3},{%4,%5,%6,%7},{%8,%9},{%0,%1,%2,%3};"
                        : "+f"(cf[rg][nt][0]), "+f"(cf[rg][nt][1]),
                          "+f"(cf[rg][nt][2]), "+f"(cf[rg][nt][3])
                        : "r"(a[rg][0]), "r"(a[rg][1]), "r"(a[rg][2]), "r"(a[rg][3]),
                          "r"(bfr[nt][0]), "r"(bfr[nt][1]));
                }
        }

#pragma unroll
        for (int rg = 0; rg < 2; rg++) {
#pragma unroll
            for (int half = 0; half < 2; half++) {
                int jl = wr * 32 + rg * 16 + gid + half * 8;
                int j  = jb + jl;
                const float* Ap = g_Ah + ((size_t)(b * Vn + j)) * Hn;
                float* Ep = eout + ((size_t)p * Vn + j) * Hn;
#pragma unroll
                for (int nt = 0; nt < 4; nt++) {
                    int h = wc * 32 + nt * 8 + tig * 2;
                    float2 ah = *(const float2*)(Ap + h);
                    float2 ei = *(const float2*)(Abuf + jl * AS_STRIDE + h);
                    float en0 = cf[rg][nt][half * 2]     + ah.x + bh8[nt * 2];
                    float en1 = cf[rg][nt][half * 2 + 1] + ah.y + bh8[nt * 2 + 1];
                    float o0 = ei.x + fmaxf(en0 * sc8[nt * 2]     + sh8[nt * 2],     0.f);
                    float o1 = ei.y + fmaxf(en1 * sc8[nt * 2 + 1] + sh8[nt * 2 + 1], 0.f);
                    *(float2*)(Ep + h) = make_float2(o0, o1);
                }
            }
        }
        __syncthreads();
    }
}

// h-side batchnorm + residual relu. One block per channel.
__global__ void k_hbn(const float* __restrict__ hin,
                      const float* __restrict__ gam,
                      const float* __restrict__ bet,
                      float* __restrict__ out) {
    int h = blockIdx.x, t = threadIdx.x;   // 256 threads
    float v[8];
    float s = 0.f, q = 0.f;
#pragma unroll
    for (int r = 0; r < 8; r++) {
        float x = g_hnew[(t * 8 + r) * Hn + h];
        v[r] = x; s += x; q += x * x;
    }
    __shared__ float rs[256], rq[256];
    rs[t] = s; rq[t] = q; __syncthreads();
    for (int o = 128; o > 0; o >>= 1) {
        if (t < o) { rs[t] += rs[t + o]; rq[t] += rq[t + o]; }
        __syncthreads();
    }
    __shared__ float sc, sh;
    if (t == 0) {
        float mean = rs[0] * (1.0f / NR);
        float var  = rq[0] * (1.0f / NR) - mean * mean;
        float scale = gam[h] * rsqrtf(var + 1e-5f);
        sc = scale; sh = bet[h] - mean * scale;
    }
    __syncthreads();
#pragma unroll
    for (int r = 0; r < 8; r++) {
        int row = t * 8 + r;
        float y = fmaxf(v[r] * sc + sh, 0.f);
        out[row * Hn + h] = hin[row * Hn + h] + y;
    }
}

__global__ void k_estats(const float* __restrict__ gam,
                         const float* __restrict__ bet) {
    int t = threadIdx.x;
    if (t < Hn) {
        float mean = g_esum[t] * (1.0f / NE);
        float var  = g_esq[t] * (1.0f / NE) - mean * mean;
        float scale = gam[t] * rsqrtf(var + 1e-5f);
        g_escale[t] = scale;
        g_eshift[t] = bet[t] - mean * scale;
    }
}

// ---------------- launch ----------------
extern "C" void kernel_launch(void* const* d_in, const int* in_sizes, int n_in,
                              void* d_out, int out_size) {
    const float* h   = (const float*)d_in[0];
    const float* e   = (const float*)d_in[1];
    const int*   gra = (const int*)  d_in[2];
    const float* Uw  = (const float*)d_in[3],  *Ub = (const float*)d_in[4];
    const float* Vw  = (const float*)d_in[5],  *Vb = (const float*)d_in[6];
    const float* Aw  = (const float*)d_in[7],  *Ab = (const float*)d_in[8];
    const float* Bw  = (const float*)d_in[9],  *Bb = (const float*)d_in[10];
    const float* Cw  = (const float*)d_in[11], *Cb = (const float*)d_in[12];
    const float* gh  = (const float*)d_in[13], *bh = (const float*)d_in[14];
    const float* ge  = (const float*)d_in[15], *be = (const float*)d_in[16];

    float* out  = (float*)d_out;
    float* hout = out;                        // [2048,128]
    float* eout = out + (size_t)NR * Hn;      // [8,256,256,128]

    const int smemE = SMEM_FLOATS * 4;        // 207360 B
    cudaFuncSetAttribute(k_pass1, cudaFuncAttributeMaxDynamicSharedMemorySize, smemE);
    cudaFuncSetAttribute(k_pass2, cudaFuncAttributeMaxDynamicSharedMemorySize, smemE);

    k_zero  <<<1, 128>>>();
    k_hlin  <<<128, 256>>>(h, Uw, Ub, Vw, Vb, Aw, Ab, Bw, Bb);
    k_pass1 <<<NR, 512, smemE>>>(e, gra, Cw, Cb);
    k_hbn   <<<Hn, 256>>>(h, gh, bh, hout);
    k_estats<<<1, 128>>>(ge, be);
    k_pass2 <<<NR, 512, smemE>>>(e, Cw, Cb, eout);
}

// round 5
// speedup vs baseline: 2.0979x; 1.1676x over previous
#include <cuda_runtime.h>
#include <math.h>
#include <stdint.h>

#define Bdim 8
#define Vn   256
#define Hn   128
#define NR   2048      /* B*V   */
#define NE   524288    /* B*V*V */

// ---------------- device scratch (no allocation allowed) ----------------
__device__ float g_Uh[NR * Hn];
__device__ float g_Vh[NR * Hn];
__device__ float g_Ah[NR * Hn];
__device__ float g_Bh[NR * Hn];
__device__ float g_hnew[NR * Hn];
__device__ float g_esum[Hn];
__device__ float g_esq[Hn];
__device__ float g_escale[Hn];
__device__ float g_eshift[Hn];
__device__ float g_enew[(size_t)NE * Hn];   // 268 MB spill of e_new

// ---------------- helpers ----------------
__device__ __forceinline__ unsigned smem_u32(const void* p) {
    unsigned a;
    asm("{ .reg .u64 t; cvta.to.shared.u64 t, %1; cvt.u32.u64 %0, t; }"
        : "=r"(a) : "l"(p));
    return a;
}
__device__ __forceinline__ void cp_async16(unsigned dst, const void* src) {
    asm volatile("cp.async.cg.shared.global [%0], [%1], 16;\n" :: "r"(dst), "l"(src));
}
__device__ __forceinline__ uint32_t f2tf32(float f) {
    uint32_t u;
    asm("cvt.rna.tf32.f32 %0, %1;" : "=r"(u) : "f"(f));
    return u;
}
__device__ __forceinline__ float fast_sigmoid(float x) {
    float t;
    asm("tanh.approx.f32 %0, %1;" : "=f"(t) : "f"(0.5f * x));
    return 0.5f * t + 0.5f;
}

// ---------------- kernels ----------------

__global__ void k_zero() {
    int t = threadIdx.x;
    if (t < Hn) { g_esum[t] = 0.f; g_esq[t] = 0.f; }
}

// two h-linears per launch (keeps pass1 at profiled stream slot 4)
#define HL_STR 132
__global__ __launch_bounds__(256)
void k_hlin2(const float* __restrict__ h,
             const float* __restrict__ W1, const float* __restrict__ b1,
             const float* __restrict__ W2, const float* __restrict__ b2,
             int which) {
    __shared__ float hs[16 * HL_STR];
    __shared__ float Ws[128 * HL_STR];
    const int t = threadIdx.x;
    const int lane = t & 31, wq = t >> 5;
    const int rbase = blockIdx.x * 16;
    {
        int idx0 = t, idx1 = t + 256;
        int r0 = idx0 >> 5, kq0 = idx0 & 31;
        int r1 = idx1 >> 5, kq1 = idx1 & 31;
        *(float4*)(hs + r0 * HL_STR + kq0 * 4) = *(const float4*)(h + (size_t)(rbase + r0) * Hn + kq0 * 4);
        *(float4*)(hs + r1 * HL_STR + kq1 * 4) = *(const float4*)(h + (size_t)(rbase + r1) * Hn + kq1 * 4);
    }
    const float* Wp[2]; const float* bp[2]; float* Op[2];
    Wp[0] = W1; Wp[1] = W2; bp[0] = b1; bp[1] = b2;
    if (which) { Op[0] = g_Ah; Op[1] = g_Bh; } else { Op[0] = g_Uh; Op[1] = g_Vh; }
    const int r0 = wq * 2, r1 = wq * 2 + 1;
    for (int a = 0; a < 2; a++) {
        __syncthreads();
        const float* W = Wp[a];
#pragma unroll
        for (int i = 0; i < 16; i++) {
            int idx = t + i * 256;
            int o = idx >> 5, kq = idx & 31;
            *(float4*)(Ws + o * HL_STR + kq * 4) = *(const float4*)(W + (size_t)o * Hn + kq * 4);
        }
        __syncthreads();
        float acc0[4] = {0.f, 0.f, 0.f, 0.f};
        float acc1[4] = {0.f, 0.f, 0.f, 0.f};
#pragma unroll 4
        for (int k4 = 0; k4 < 32; k4++) {
            float4 h0 = *(const float4*)(hs + r0 * HL_STR + k4 * 4);
            float4 h1 = *(const float4*)(hs + r1 * HL_STR + k4 * 4);
#pragma unroll
            for (int c = 0; c < 4; c++) {
                float4 w = *(const float4*)(Ws + (lane + 32 * c) * HL_STR + k4 * 4);
                acc0[c] += h0.x * w.x + h0.y * w.y + h0.z * w.z + h0.w * w.w;
                acc1[c] += h1.x * w.x + h1.y * w.y + h1.z * w.z + h1.w * w.w;
            }
        }
        float* O = Op[a];
        const float* bb = bp[a];
#pragma unroll
        for (int c = 0; c < 4; c++) {
            int col = lane + 32 * c;
            float bv = bb[col];
            O[(size_t)(rbase + r0) * Hn + col] = acc0[c] + bv;
            O[(size_t)(rbase + r1) * Hn + col] = acc1[c] + bv;
        }
    }
}

// Pass 1: tf32 mma.sync GEMM + fused epilogue.
// One block per p=(b,i). 512 threads = 16 warps (4x4), warp tile 32x32,
// j in 2 chunks of 128 rows, K=128 (16 ksteps of k8).
// A-fragments: raw fp32 bits (HW truncates to tf32). B (Cw) staged with cvt.rna.
#define WT_STRIDE 136
#define AS_STRIDE 132
#define AS_OFF    17408
#define AS_BUF    16896
#define SUM_OFF   51200
#define SMEM_FLOATS 51840

__global__ __launch_bounds__(512, 1)
void k_pass1(const float* __restrict__ e,
             const int* __restrict__ graph,
             const float* __restrict__ Cw,
             const float* __restrict__ Cb) {
    extern __shared__ float sm[];
    uint32_t* WtS = (uint32_t*)sm;
    float* As   = sm + AS_OFF;
    float* sumS = sm + SUM_OFF;
    float* sqS  = sumS + 128;
    float* aggS = sqS + 128;
    int*   gs   = (int*)(aggS + 128);

    const int p = blockIdx.x;
    const int b = p >> 8;
    const int t = threadIdx.x;
    const int lane = t & 31;
    const int wid  = t >> 5;
    const int wr = wid >> 2, wc = wid & 3;
    const int gid = lane >> 2, tig = lane & 3;

    for (int i = t; i < Hn * Hn; i += 512) {
        int n = i >> 7, k = i & 127;
        WtS[k * WT_STRIDE + n] = f2tf32(Cw[i]);
    }
    if (t < 256) gs[t] = graph[p * Vn + t];
    if (t < 128) { sumS[t] = 0.f; sqS[t] = 0.f; aggS[t] = 0.f; }

    float bh8[8];
#pragma unroll
    for (int q = 0; q < 4; q++) {
        int h = wc * 32 + q * 8 + tig * 2;
        float2 bb = *(const float2*)(g_Bh + p * Hn + h);
        float2 cb = *(const float2*)(Cb + h);
        bh8[q * 2]     = bb.x + cb.x;
        bh8[q * 2 + 1] = bb.y + cb.y;
    }

    float sum8[8], sq8[8], agg8[8];
#pragma unroll
    for (int i = 0; i < 8; i++) { sum8[i] = 0.f; sq8[i] = 0.f; agg8[i] = 0.f; }

    const float* ebase = e + (size_t)p * Vn * Hn;
    {
        unsigned dbase = smem_u32(As);
#pragma unroll
        for (int i = 0; i < 8; i++) {
            int fid = i * 512 + t;
            int row = fid >> 5, kq = fid & 31;
            cp_async16(dbase + (row * AS_STRIDE + kq * 4) * 4,
                       ebase + (size_t)row * Hn + kq * 4);
        }
        asm volatile("cp.async.commit_group;\n");
    }

    for (int c = 0; c < 2; c++) {
        if (c == 0) {
            unsigned dbase = smem_u32(As + AS_BUF);
#pragma unroll
            for (int i = 0; i < 8; i++) {
                int fid = i * 512 + t;
                int row = fid >> 5, kq = fid & 31;
                cp_async16(dbase + (row * AS_STRIDE + kq * 4) * 4,
                           ebase + (size_t)(128 + row) * Hn + kq * 4);
            }
            asm volatile("cp.async.commit_group;\n");
            asm volatile("cp.async.wait_group 1;\n");
        } else {
            asm volatile("cp.async.wait_group 0;\n");
        }
        __syncthreads();

        const float* Abuf = As + c * AS_BUF;
        const uint32_t* AbufU = (const uint32_t*)Abuf;
        const int jb = c * 128;

        float cf[2][4][4];
#pragma unroll
        for (int rg = 0; rg < 2; rg++)
#pragma unroll
            for (int nt = 0; nt < 4; nt++)
#pragma unroll
                for (int q = 0; q < 4; q++) cf[rg][nt][q] = 0.f;

#pragma unroll 2
        for (int ks = 0; ks < 16; ks++) {
            int k0 = ks * 8 + tig;
            uint32_t a[2][4];
#pragma unroll
            for (int rg = 0; rg < 2; rg++) {
                int r = wr * 32 + rg * 16 + gid;
                a[rg][0] = AbufU[r * AS_STRIDE + k0];        // raw fp32 bits
                a[rg][1] = AbufU[(r + 8) * AS_STRIDE + k0];
                a[rg][2] = AbufU[r * AS_STRIDE + k0 + 4];
                a[rg][3] = AbufU[(r + 8) * AS_STRIDE + k0 + 4];
            }
            uint32_t bfr[4][2];
#pragma unroll
            for (int nt = 0; nt < 4; nt++) {
                int n = wc * 32 + nt * 8 + gid;
                bfr[nt][0] = WtS[k0 * WT_STRIDE + n];
                bfr[nt][1] = WtS[(k0 + 4) * WT_STRIDE + n];
            }
#pragma unroll
            for (int rg = 0; rg < 2; rg++)
#pragma unroll
                for (int nt = 0; nt < 4; nt++) {
                    asm volatile(
                        "mma.sync.aligned.m16n8k8.row.col.f32.tf32.tf32.f32 "
                        "{%0,%1,%2,%3},{%4,%5,%6,%7},{%8,%9},{%0,%1,%2,%3};"
                        : "+f"(cf[rg][nt][0]), "+f"(cf[rg][nt][1]),
                          "+f"(cf[rg][nt][2]), "+f"(cf[rg][nt][3])
                        : "r"(a[rg][0]), "r"(a[rg][1]), "r"(a[rg][2]), "r"(a[rg][3]),
                          "r"(bfr[nt][0]), "r"(bfr[nt][1]));
                }
        }

#pragma unroll
        for (int rg = 0; rg < 2; rg++) {
#pragma unroll
            for (int half = 0; half < 2; half++) {
                int jl = wr * 32 + rg * 16 + gid + half * 8;
                int j  = jb + jl;
                int gmask = gs[j];
                const float* Ap = g_Ah + ((size_t)(b * Vn + j)) * Hn;
                const float* Vp = g_Vh + ((size_t)(b * Vn + j)) * Hn;
                float* Ep = g_enew + ((size_t)p * Vn + j) * Hn;
#pragma unroll
                for (int nt = 0; nt < 4; nt++) {
                    int h = wc * 32 + nt * 8 + tig * 2;
                    float2 ah = *(const float2*)(Ap + h);
                    float2 vh = *(const float2*)(Vp + h);
                    float en0 = cf[rg][nt][half * 2]     + ah.x + bh8[nt * 2];
                    float en1 = cf[rg][nt][half * 2 + 1] + ah.y + bh8[nt * 2 + 1];
                    *(float2*)(Ep + h) = make_float2(en0, en1);
                    sum8[nt * 2]     += en0;
                    sum8[nt * 2 + 1] += en1;
                    sq8[nt * 2]      += en0 * en0;
                    sq8[nt * 2 + 1]  += en1 * en1;
                    if (!gmask) {
                        agg8[nt * 2]     += fast_sigmoid(en0) * vh.x;
                        agg8[nt * 2 + 1] += fast_sigmoid(en1) * vh.y;
                    }
                }
            }
        }
        __syncthreads();
    }

#pragma unroll
    for (int i = 0; i < 8; i++) {
        int h = wc * 32 + (i >> 1) * 8 + tig * 2 + (i & 1);
        atomicAdd(&sumS[h], sum8[i]);
        atomicAdd(&sqS[h],  sq8[i]);
        atomicAdd(&aggS[h], agg8[i]);
    }
    __syncthreads();
    if (t < Hn) {
        atomicAdd(&g_esum[t], sumS[t]);
        atomicAdd(&g_esq[t],  sqS[t]);
        g_hnew[p * Hn + t] = g_Uh[p * Hn + t] + aggS[t];
    }
}

// h-side batchnorm + residual relu. One block per channel.
__global__ void k_hbn(const float* __restrict__ hin,
                      const float* __restrict__ gam,
                      const float* __restrict__ bet,
                      float* __restrict__ out) {
    int h = blockIdx.x, t = threadIdx.x;
    float v[8];
    float s = 0.f, q = 0.f;
#pragma unroll
    for (int r = 0; r < 8; r++) {
        float x = g_hnew[(size_t)(t * 8 + r) * Hn + h];
        v[r] = x; s += x; q += x * x;
    }
    __shared__ float rs[256], rq[256];
    rs[t] = s; rq[t] = q; __syncthreads();
    for (int o = 128; o > 0; o >>= 1) {
        if (t < o) { rs[t] += rs[t + o]; rq[t] += rq[t + o]; }
        __syncthreads();
    }
    __shared__ float sc, sh;
    if (t == 0) {
        float mean = rs[0] * (1.0f / NR);
        float var  = rq[0] * (1.0f / NR) - mean * mean;
        float scale = gam[h] * rsqrtf(var + 1e-5f);
        sc = scale; sh = bet[h] - mean * scale;
    }
    __syncthreads();
#pragma unroll
    for (int r = 0; r < 8; r++) {
        int row = t * 8 + r;
        float y = fmaxf(v[r] * sc + sh, 0.f);
        out[(size_t)row * Hn + h] = hin[(size_t)row * Hn + h] + y;
    }
}

__global__ void k_estats(const float* __restrict__ gam,
                         const float* __restrict__ bet) {
    int t = threadIdx.x;
    if (t < Hn) {
        float mean = g_esum[t] * (1.0f / NE);
        float var  = g_esq[t] * (1.0f / NE) - mean * mean;
        float scale = gam[t] * rsqrtf(var + 1e-5f);
        g_escale[t] = scale;
        g_eshift[t] = bet[t] - mean * scale;
    }
}

// pass 2 over e: normalize + relu + residual, pure streaming float4
__global__ void k_epass2(const float* __restrict__ ein,
                         float* __restrict__ eout) {
    size_t idx = (size_t)blockIdx.x * blockDim.x + threadIdx.x;  // float4 idx
    int h0 = (int)((idx * 4) & 127);
    float4 x = ((const float4*)g_enew)[idx];
    float4 a = ((const float4*)ein)[idx];
    float4 o;
    o.x = a.x + fmaxf(x.x * g_escale[h0]     + g_eshift[h0],     0.f);
    o.y = a.y + fmaxf(x.y * g_escale[h0 + 1] + g_eshift[h0 + 1], 0.f);
    o.z = a.z + fmaxf(x.z * g_escale[h0 + 2] + g_eshift[h0 + 2], 0.f);
    o.w = a.w + fmaxf(x.w * g_escale[h0 + 3] + g_eshift[h0 + 3], 0.f);
    ((float4*)eout)[idx] = o;
}

// ---------------- launch ----------------
extern "C" void kernel_launch(void* const* d_in, const int* in_sizes, int n_in,
                              void* d_out, int out_size) {
    const float* h   = (const float*)d_in[0];
    const float* e   = (const float*)d_in[1];
    const int*   gra = (const int*)  d_in[2];
    const float* Uw  = (const float*)d_in[3],  *Ub = (const float*)d_in[4];
    const float* Vw  = (const float*)d_in[5],  *Vb = (const float*)d_in[6];
    const float* Aw  = (const float*)d_in[7],  *Ab = (const float*)d_in[8];
    const float* Bw  = (const float*)d_in[9],  *Bb = (const float*)d_in[10];
    const float* Cw  = (const float*)d_in[11], *Cb = (const float*)d_in[12];
    const float* gh  = (const float*)d_in[13], *bh = (const float*)d_in[14];
    const float* ge  = (const float*)d_in[15], *be = (const float*)d_in[16];

    float* out  = (float*)d_out;
    float* hout = out;                        // [2048,128]
    float* eout = out + (size_t)NR * Hn;      // [8,256,256,128]

    const int smemE = SMEM_FLOATS * 4;        // 207360 B
    cudaFuncSetAttribute(k_pass1, cudaFuncAttributeMaxDynamicSharedMemorySize, smemE);

    k_zero  <<<1, 128>>>();
    k_hlin2 <<<128, 256>>>(h, Uw, Ub, Vw, Vb, 0);
    k_hlin2 <<<128, 256>>>(h, Aw, Ab, Bw, Bb, 1);
    k_pass1 <<<NR, 512, smemE>>>(e, gra, Cw, Cb);
    k_hbn   <<<Hn, 256>>>(h, gh, bh, hout);
    k_estats<<<1, 128>>>(ge, be);
    k_epass2<<<65536, 256>>>(e, eout);
}

// round 6
// speedup vs baseline: 3.3969x; 1.6192x over previous
#include <cuda_runtime.h>
#include <math.h>
#include <stdint.h>

#define Bdim 8
#define Vn   256
#define Hn   128
#define NR   2048      /* B*V   */
#define NE   524288    /* B*V*V */

// ---------------- device scratch (no allocation allowed) ----------------
__device__ float g_Uh[NR * Hn];
__device__ float g_Vh[NR * Hn];
__device__ float g_Ah[NR * Hn];
__device__ float g_Bh[NR * Hn];
__device__ float g_hnew[NR * Hn];
__device__ float g_esum[Hn];
__device__ float g_esq[Hn];
__device__ float g_escale[Hn];
__device__ float g_eshift[Hn];
__device__ float g_enew[(size_t)NE * Hn];   // 268 MB spill of e_new

// ---------------- helpers ----------------
__device__ __forceinline__ unsigned smem_u32(const void* p) {
    unsigned a;
    asm("{ .reg .u64 t; cvta.to.shared.u64 t, %1; cvt.u32.u64 %0, t; }"
        : "=r"(a) : "l"(p));
    return a;
}
__device__ __forceinline__ void cp_async16(unsigned dst, const void* src) {
    asm volatile("cp.async.cg.shared.global [%0], [%1], 16;\n" :: "r"(dst), "l"(src));
}
__device__ __forceinline__ uint32_t f2tf32(float f) {
    uint32_t u;
    asm("cvt.rna.tf32.f32 %0, %1;" : "=r"(u) : "f"(f));
    return u;
}
__device__ __forceinline__ float fast_sigmoid(float x) {
    float t;
    asm("tanh.approx.f32 %0, %1;" : "=f"(t) : "f"(0.5f * x));
    return 0.5f * t + 0.5f;
}

// ---------------- kernels ----------------

__global__ void k_zero() {
    int t = threadIdx.x;
    if (t < Hn) { g_esum[t] = 0.f; g_esq[t] = 0.f; }
}

// two h-linears per launch (keeps pass1 at profiled stream slot 4)
#define HL_STR 132
__global__ __launch_bounds__(256)
void k_hlin2(const float* __restrict__ h,
             const float* __restrict__ W1, const float* __restrict__ b1,
             const float* __restrict__ W2, const float* __restrict__ b2,
             int which) {
    __shared__ float hs[16 * HL_STR];
    __shared__ float Ws[128 * HL_STR];
    const int t = threadIdx.x;
    const int lane = t & 31, wq = t >> 5;
    const int rbase = blockIdx.x * 16;
    {
        int idx0 = t, idx1 = t + 256;
        int r0 = idx0 >> 5, kq0 = idx0 & 31;
        int r1 = idx1 >> 5, kq1 = idx1 & 31;
        *(float4*)(hs + r0 * HL_STR + kq0 * 4) = *(const float4*)(h + (size_t)(rbase + r0) * Hn + kq0 * 4);
        *(float4*)(hs + r1 * HL_STR + kq1 * 4) = *(const float4*)(h + (size_t)(rbase + r1) * Hn + kq1 * 4);
    }
    const float* Wp[2]; const float* bp[2]; float* Op[2];
    Wp[0] = W1; Wp[1] = W2; bp[0] = b1; bp[1] = b2;
    if (which) { Op[0] = g_Ah; Op[1] = g_Bh; } else { Op[0] = g_Uh; Op[1] = g_Vh; }
    const int r0 = wq * 2, r1 = wq * 2 + 1;
    for (int a = 0; a < 2; a++) {
        __syncthreads();
        const float* W = Wp[a];
#pragma unroll
        for (int i = 0; i < 16; i++) {
            int idx = t + i * 256;
            int o = idx >> 5, kq = idx & 31;
            *(float4*)(Ws + o * HL_STR + kq * 4) = *(const float4*)(W + (size_t)o * Hn + kq * 4);
        }
        __syncthreads();
        float acc0[4] = {0.f, 0.f, 0.f, 0.f};
        float acc1[4] = {0.f, 0.f, 0.f, 0.f};
#pragma unroll 4
        for (int k4 = 0; k4 < 32; k4++) {
            float4 h0 = *(const float4*)(hs + r0 * HL_STR + k4 * 4);
            float4 h1 = *(const float4*)(hs + r1 * HL_STR + k4 * 4);
#pragma unroll
            for (int c = 0; c < 4; c++) {
                float4 w = *(const float4*)(Ws + (lane + 32 * c) * HL_STR + k4 * 4);
                acc0[c] += h0.x * w.x + h0.y * w.y + h0.z * w.z + h0.w * w.w;
                acc1[c] += h1.x * w.x + h1.y * w.y + h1.z * w.z + h1.w * w.w;
            }
        }
        float* O = Op[a];
        const float* bb = bp[a];
#pragma unroll
        for (int c = 0; c < 4; c++) {
            int col = lane + 32 * c;
            float bv = bb[col];
            O[(size_t)(rbase + r0) * Hn + col] = acc0[c] + bv;
            O[(size_t)(rbase + r1) * Hn + col] = acc1[c] + bv;
        }
    }
}

// Pass 1: tf32 mma.sync GEMM + coalesced fused epilogue.
// One block per p=(b,i). 512 threads = 16 warps (4x4), warp tile 32x32,
// j in 2 chunks of 128 rows, K=128 (16 ksteps of k8).
// After the K-loop, fragments are transposed through the dead e-tile smem
// buffer so the epilogue is row-major: every LDG/STG/LDS is 128B per warp.
#define WT_STRIDE 136
#define AS_STRIDE 132
#define AS_OFF    17408
#define AS_BUF    16896
#define SUM_OFF   51200
#define SMEM_FLOATS 51840
// reduction scratch inside retired WtS area (floats):
#define RED_SQ    2112
#define RED_AGG   4224

__global__ __launch_bounds__(512, 1)
void k_pass1(const float* __restrict__ e,
             const int* __restrict__ graph,
             const float* __restrict__ Cw,
             const float* __restrict__ Cb) {
    extern __shared__ float sm[];
    uint32_t* WtS = (uint32_t*)sm;
    float* As   = sm + AS_OFF;
    int*   gs   = (int*)(sm + SUM_OFF);   // 256 ints

    const int p = blockIdx.x;
    const int b = p >> 8;
    const int t = threadIdx.x;
    const int lane = t & 31;
    const int wid  = t >> 5;
    const int wr = wid >> 2, wc = wid & 3;
    const int gid = lane >> 2, tig = lane & 3;

    for (int i = t; i < Hn * Hn; i += 512) {
        int n = i >> 7, k = i & 127;
        WtS[k * WT_STRIDE + n] = f2tf32(Cw[i]);
    }
    if (t < 256) gs[t] = graph[p * Vn + t];

    // per-lane bias for 4 channels h = lane*4..lane*4+3
    const int h4 = lane * 4;
    float4 bias4;
    {
        float4 bb = *(const float4*)(g_Bh + (size_t)p * Hn + h4);
        float4 cb = *(const float4*)(Cb + h4);
        bias4 = make_float4(bb.x + cb.x, bb.y + cb.y, bb.z + cb.z, bb.w + cb.w);
    }

    float4 sum4 = make_float4(0.f, 0.f, 0.f, 0.f);
    float4 sq4  = make_float4(0.f, 0.f, 0.f, 0.f);
    float4 agg4 = make_float4(0.f, 0.f, 0.f, 0.f);

    const float* ebase = e + (size_t)p * Vn * Hn;
    {
        unsigned dbase = smem_u32(As);
#pragma unroll
        for (int i = 0; i < 8; i++) {
            int fid = i * 512 + t;
            int row = fid >> 5, kq = fid & 31;
            cp_async16(dbase + (row * AS_STRIDE + kq * 4) * 4,
                       ebase + (size_t)row * Hn + kq * 4);
        }
        asm volatile("cp.async.commit_group;\n");
    }

    for (int c = 0; c < 2; c++) {
        if (c == 0) {
            unsigned dbase = smem_u32(As + AS_BUF);
#pragma unroll
            for (int i = 0; i < 8; i++) {
                int fid = i * 512 + t;
                int row = fid >> 5, kq = fid & 31;
                cp_async16(dbase + (row * AS_STRIDE + kq * 4) * 4,
                           ebase + (size_t)(128 + row) * Hn + kq * 4);
            }
            asm volatile("cp.async.commit_group;\n");
            asm volatile("cp.async.wait_group 1;\n");
        } else {
            asm volatile("cp.async.wait_group 0;\n");
        }
        __syncthreads();

        float* Abuf = As + c * AS_BUF;
        const uint32_t* AbufU = (const uint32_t*)Abuf;
        const int jb = c * 128;

        float cf[2][4][4];
#pragma unroll
        for (int rg = 0; rg < 2; rg++)
#pragma unroll
            for (int nt = 0; nt < 4; nt++)
#pragma unroll
                for (int q = 0; q < 4; q++) cf[rg][nt][q] = 0.f;

#pragma unroll 2
        for (int ks = 0; ks < 16; ks++) {
            int k0 = ks * 8 + tig;
            uint32_t a[2][4];
#pragma unroll
            for (int rg = 0; rg < 2; rg++) {
                int r = wr * 32 + rg * 16 + gid;
                a[rg][0] = AbufU[r * AS_STRIDE + k0];        // raw fp32 bits (HW->tf32)
                a[rg][1] = AbufU[(r + 8) * AS_STRIDE + k0];
                a[rg][2] = AbufU[r * AS_STRIDE + k0 + 4];
                a[rg][3] = AbufU[(r + 8) * AS_STRIDE + k0 + 4];
            }
            uint32_t bfr[4][2];
#pragma unroll
            for (int nt = 0; nt < 4; nt++) {
                int n = wc * 32 + nt * 8 + gid;
                bfr[nt][0] = WtS[k0 * WT_STRIDE + n];
                bfr[nt][1] = WtS[(k0 + 4) * WT_STRIDE + n];
            }
#pragma unroll
            for (int rg = 0; rg < 2; rg++)
#pragma unroll
                for (int nt = 0; nt < 4; nt++) {
                    asm volatile(
                        "mma.sync.aligned.m16n8k8.row.col.f32.tf32.tf32.f32 "
                        "{%0,%1,%2,%3},{%4,%5,%6,%7},{%8,%9},{%0,%1,%2,%3};"
                        : "+f"(cf[rg][nt][0]), "+f"(cf[rg][nt][1]),
                          "+f"(cf[rg][nt][2]), "+f"(cf[rg][nt][3])
                        : "r"(a[rg][0]), "r"(a[rg][1]), "r"(a[rg][2]), "r"(a[rg][3]),
                          "r"(bfr[nt][0]), "r"(bfr[nt][1]));
                }
        }

        // ---- transpose fragments into the dead e-tile buffer ----
        __syncthreads();   // all warps done reading Abuf
#pragma unroll
        for (int rg = 0; rg < 2; rg++)
#pragma unroll
            for (int half = 0; half < 2; half++) {
                int jl = wr * 32 + rg * 16 + half * 8 + gid;
#pragma unroll
                for (int nt = 0; nt < 4; nt++) {
                    int h = wc * 32 + nt * 8 + tig * 2;
                    *(float2*)(Abuf + jl * AS_STRIDE + h) =
                        make_float2(cf[rg][nt][half * 2], cf[rg][nt][half * 2 + 1]);
                }
            }
        __syncthreads();

        // ---- coalesced epilogue: warp owns rows [wid*8, wid*8+8) ----
        const float* AhB = g_Ah + (size_t)b * Vn * Hn;
        const float* VhB = g_Vh + (size_t)b * Vn * Hn;
#pragma unroll
        for (int r = 0; r < 8; r++) {
            int jl = wid * 8 + r;
            int j  = jb + jl;
            float4 cv = *(const float4*)(Abuf + jl * AS_STRIDE + h4);
            float4 ah = *(const float4*)(AhB + (size_t)j * Hn + h4);
            float4 en;
            en.x = cv.x + ah.x + bias4.x;
            en.y = cv.y + ah.y + bias4.y;
            en.z = cv.z + ah.z + bias4.z;
            en.w = cv.w + ah.w + bias4.w;
            *(float4*)(g_enew + ((size_t)p * Vn + j) * Hn + h4) = en;
            sum4.x += en.x; sum4.y += en.y; sum4.z += en.z; sum4.w += en.w;
            sq4.x += en.x * en.x; sq4.y += en.y * en.y;
            sq4.z += en.z * en.z; sq4.w += en.w * en.w;
            if (!gs[j]) {
                float4 vh = *(const float4*)(VhB + (size_t)j * Hn + h4);
                agg4.x += fast_sigmoid(en.x) * vh.x;
                agg4.y += fast_sigmoid(en.y) * vh.y;
                agg4.z += fast_sigmoid(en.z) * vh.z;
                agg4.w += fast_sigmoid(en.w) * vh.w;
            }
        }
        __syncthreads();
    }

    // ---- block reduction via retired WtS area ----
    float* redS = sm;
    *(float4*)(redS + wid * AS_STRIDE + h4)           = sum4;
    *(float4*)(redS + RED_SQ + wid * AS_STRIDE + h4)  = sq4;
    *(float4*)(redS + RED_AGG + wid * AS_STRIDE + h4) = agg4;
    __syncthreads();
    if (t < Hn) {
        float s = 0.f, q = 0.f, g = 0.f;
#pragma unroll
        for (int w = 0; w < 16; w++) {
            s += redS[w * AS_STRIDE + t];
            q += redS[RED_SQ + w * AS_STRIDE + t];
            g += redS[RED_AGG + w * AS_STRIDE + t];
        }
        atomicAdd(&g_esum[t], s);
        atomicAdd(&g_esq[t],  q);
        g_hnew[(size_t)p * Hn + t] = g_Uh[(size_t)p * Hn + t] + g;
    }
}

// h-side batchnorm + residual relu. One block per channel.
__global__ void k_hbn(const float* __restrict__ hin,
                      const float* __restrict__ gam,
                      const float* __restrict__ bet,
                      float* __restrict__ out) {
    int h = blockIdx.x, t = threadIdx.x;
    float v[8];
    float s = 0.f, q = 0.f;
#pragma unroll
    for (int r = 0; r < 8; r++) {
        float x = g_hnew[(size_t)(t * 8 + r) * Hn + h];
        v[r] = x; s += x; q += x * x;
    }
    __shared__ float rs[256], rq[256];
    rs[t] = s; rq[t] = q; __syncthreads();
    for (int o = 128; o > 0; o >>= 1) {
        if (t < o) { rs[t] += rs[t + o]; rq[t] += rq[t + o]; }
        __syncthreads();
    }
    __shared__ float sc, sh;
    if (t == 0) {
        float mean = rs[0] * (1.0f / NR);
        float var  = rq[0] * (1.0f / NR) - mean * mean;
        float scale = gam[h] * rsqrtf(var + 1e-5f);
        sc = scale; sh = bet[h] - mean * scale;
    }
    __syncthreads();
#pragma unroll
    for (int r = 0; r < 8; r++) {
        int row = t * 8 + r;
        float y = fmaxf(v[r] * sc + sh, 0.f);
        out[(size_t)row * Hn + h] = hin[(size_t)row * Hn + h] + y;
    }
}

__global__ void k_estats(const float* __restrict__ gam,
                         const float* __restrict__ bet) {
    int t = threadIdx.x;
    if (t < Hn) {
        float mean = g_esum[t] * (1.0f / NE);
        float var  = g_esq[t] * (1.0f / NE) - mean * mean;
        float scale = gam[t] * rsqrtf(var + 1e-5f);
        g_escale[t] = scale;
        g_eshift[t] = bet[t] - mean * scale;
    }
}

// pass 2 over e: normalize + relu + residual, pure streaming float4
__global__ void k_epass2(const float* __restrict__ ein,
                         float* __restrict__ eout) {
    size_t idx = (size_t)blockIdx.x * blockDim.x + threadIdx.x;  // float4 idx
    int h0 = (int)((idx * 4) & 127);
    float4 x = ((const float4*)g_enew)[idx];
    float4 a = ((const float4*)ein)[idx];
    float4 o;
    o.x = a.x + fmaxf(x.x * g_escale[h0]     + g_eshift[h0],     0.f);
    o.y = a.y + fmaxf(x.y * g_escale[h0 + 1] + g_eshift[h0 + 1], 0.f);
    o.z = a.z + fmaxf(x.z * g_escale[h0 + 2] + g_eshift[h0 + 2], 0.f);
    o.w = a.w + fmaxf(x.w * g_escale[h0 + 3] + g_eshift[h0 + 3], 0.f);
    ((float4*)eout)[idx] = o;
}

// ---------------- launch ----------------
extern "C" void kernel_launch(void* const* d_in, const int* in_sizes, int n_in,
                              void* d_out, int out_size) {
    const float* h   = (const float*)d_in[0];
    const float* e   = (const float*)d_in[1];
    const int*   gra = (const int*)  d_in[2];
    const float* Uw  = (const float*)d_in[3],  *Ub = (const float*)d_in[4];
    const float* Vw  = (const float*)d_in[5],  *Vb = (const float*)d_in[6];
    const float* Aw  = (const float*)d_in[7],  *Ab = (const float*)d_in[8];
    const float* Bw  = (const float*)d_in[9],  *Bb = (const float*)d_in[10];
    const float* Cw  = (const float*)d_in[11], *Cb = (const float*)d_in[12];
    const float* gh  = (const float*)d_in[13], *bh = (const float*)d_in[14];
    const float* ge  = (const float*)d_in[15], *be = (const float*)d_in[16];

    float* out  = (float*)d_out;
    float* hout = out;                        // [2048,128]
    float* eout = out + (size_t)NR * Hn;      // [8,256,256,128]

    const int smemE = SMEM_FLOATS * 4;        // 207360 B
    cudaFuncSetAttribute(k_pass1, cudaFuncAttributeMaxDynamicSharedMemorySize, smemE);

    k_zero  <<<1, 128>>>();
    k_hlin2 <<<128, 256>>>(h, Uw, Ub, Vw, Vb, 0);
    k_hlin2 <<<128, 256>>>(h, Aw, Ab, Bw, Bb, 1);
    k_pass1 <<<NR, 512, smemE>>>(e, gra, Cw, Cb);
    k_hbn   <<<Hn, 256>>>(h, gh, bh, hout);
    k_estats<<<1, 128>>>(ge, be);
    k_epass2<<<65536, 256>>>(e, eout);
}